// round 11
// baseline (speedup 1.0000x reference)
#include <cuda_runtime.h>

namespace {
constexpr int K     = 9;
constexpr int NB    = 64;
constexpr int NH    = 32;
constexpr int NW    = 32;
constexpr int NCELL = NH * NW;       // 1024
constexpr int NT    = 50;
constexpr int NLAB  = 2 * K + 3;     // 21
constexpr int CH    = 2 * K + 2;     // 20
constexpr float THR = 80.0f;
constexpr float IMW = 640.0f;
constexpr float IMH = 480.0f;
constexpr float SIL = 0.6f;
constexpr float OBJ = 5.0f;
constexpr int   TPB  = 1024;         // 2 threads per cell (paired lanes)
constexpr int   NBLK = 128;          // 128 CTAs, 1/SM, single wave
constexpr float CELLW = IMW / NW;    // 20 px
constexpr float CELLH = IMH / NH;    // 15 px
constexpr float THR2  = THR * THR;   // 6400
constexpr float GATE2 = 40.0f * 40.0f;  // silent needs >=5 corners within 40px
constexpr unsigned FULL = 0xffffffffu;
}

__device__ float        g_partials[NBLK];
__device__ unsigned int g_count = 0;

__global__ __launch_bounds__(TPB, 1) void region_loss_kernel(
    const float* __restrict__ out,
    const float* __restrict__ tgt,
    const int*   __restrict__ epoch_p,
    float*       __restrict__ loss)
{
    __shared__ float2 sXY[NT][K];                  // gt corners, pixel space
    __shared__ float swarp[TPB / 32];
    __shared__ int   s_last;

    const int bid  = blockIdx.x;
    const int b    = bid >> 1;
    const int tid  = threadIdx.x;
    const int lane = tid & 31;
    const int sub  = lane >> 4;                    // 0: corners 0-4, 1: corners 5-8
    const int wid  = tid >> 5;                     // warp covers 16 cells
    const int cell = ((bid & 1) << 9) | (wid << 4) | (lane & 15);
    const int wbase = cell & ~15;

    // ---- 1) loads first: 10 symmetric channels per thread
    const int epoch = epoch_p ? __ldg(epoch_p) : 20;
    const float* ob = out + (size_t)(b * CH) * NCELL + cell;
    float rx[5], ry[5];
    #pragma unroll
    for (int k = 0; k < 5; k++) {
        rx[k] = ob[(sub * 10 + 2 * k) * NCELL];
        ry[k] = ob[(sub * 10 + 2 * k + 1) * NCELL];
    }

    // ---- 2) stage targets (coalesced), pixel space — single barrier
    const float* tb = tgt + (size_t)b * (NT * NLAB);
    if (tid < NT * 2 * K) {
        int t = tid / (2 * K), c = tid - t * (2 * K);
        float v = tb[t * NLAB + 1 + c];
        float* dst = (float*)&sXY[t][c >> 1];
        dst[c & 1] = v * ((c & 1) ? IMH : IMW);
    }
    __syncthreads();

    // ---- 3) validity prefix + per-warp hit detection (lane-parallel, t<32)
    float2 c0l = sXY[lane][0];
    unsigned inv0 = ~__ballot_sync(FULL, c0l.x != 0.0f);
    bool v2 = (lane + 32 < NT) && (sXY[lane + 32][0].x != 0.0f);
    unsigned inv1 = ~__ballot_sync(FULL, v2);      // bits >= NT-32 always set
    const int nv = inv0 ? (__ffs(inv0) - 1) : (31 + __ffs(inv1));

    int gi0l = (int)floorf(c0l.x * (1.0f / CELLW));
    int gj0l = (int)floorf(c0l.y * (1.0f / CELLH));
    int cellv = (gi0l >= 0 && gi0l < NW && gj0l >= 0 && gj0l < NH)
                    ? gj0l * NW + gi0l : -1;
    cellv = (lane < nv) ? cellv : -1;
    unsigned hitm = __ballot_sync(FULL, (cellv >= wbase) && (cellv < wbase + 16));
    int thit = -1;
    for (unsigned hm = hitm; hm; hm &= hm - 1) {   // ascending t: last wins
        int t  = __ffs(hm) - 1;
        int sc = __shfl_sync(FULL, cellv, t);
        thit = (sc == cell) ? t : thit;
    }

    // ---- 4) predictions in pixel space (only global corner 0 is sigmoided)
    const bool do_conf = epoch > 15;
    const float i_f = (float)(cell & (NW - 1));
    const float j_f = (float)(cell >> 5);
    if (!sub) {
        rx[0] = 1.0f / (1.0f + __expf(-rx[0]));
        ry[0] = 1.0f / (1.0f + __expf(-ry[0]));
    }
    float confp = 1.0f / (1.0f + __expf(-__shfl_xor_sync(FULL, rx[4], 16)));

    float px[5], py[5];
    #pragma unroll
    for (int k = 0; k < 5; k++) {
        px[k] = (rx[k] + i_f) * CELLW;
        py[k] = (ry[k] + j_f) * CELLH;
    }

    const float inv_denK = (1.0f / (float)K) / (__expf(2.0f) - 1.0f + 1e-5f);

    // ---- 5) silent loop, targets t<32, in GROUPS OF 8 with packed 4-bit
    // counts: one pair-combine shfl + one REDUX per group instead of per target.
    bool silent = false;
    const int tmax = nv < 32 ? nv : 32;
    for (int g = 0; g < tmax; g += 8) {
        const int nvg = (tmax - g) < 8 ? (tmax - g) : 8;
        // validity mask on nibble-bit3 positions for this group
        const unsigned vmask = (nvg == 8) ? 0x88888888u
                              : (((1u << (4 * nvg)) - 1u) & 0x88888888u);
        unsigned word = 0;
        #pragma unroll
        for (int tl = 0; tl < 8; tl++) {
            int t = g + tl;
            unsigned cnt = 0;
            #pragma unroll
            for (int k = 0; k < 5; k++) {
                int kk = k + (sub ? 5 : 0); kk = kk > 8 ? 8 : kk;
                float2 gc = sXY[t][kk];
                float dx = gc.x - px[k], dy = gc.y - py[k];
                float d2 = fmaf(dx, dx, dy * dy);
                if (k == 4) d2 = sub ? 3.0e38f : d2;   // mask dummy corner
                cnt += (d2 < GATE2);
            }
            word |= cnt << (4 * tl);
        }
        unsigned sum = word + __shfl_xor_sync(FULL, word, 16);  // nibble sums <= 10
        // nibble >= 5  <=>  bit3 of (nibble+3); exact gate for mean-conf > 0.6
        unsigned hotbits = ((sum + 0x33333333u) & 0x88888888u) & vmask;
        unsigned un = __reduce_or_sync(FULL, hotbits);          // warp union
        while (un) {                                            // rare, converged
            int p  = __ffs(un) - 1;                             // = 4*tl + 3
            un &= un - 1;
            int t  = g + (p >> 2);
            float acc = 0.0f;
            #pragma unroll
            for (int k = 0; k < 5; k++) {
                int kk = k + (sub ? 5 : 0); kk = kk > 8 ? 8 : kk;
                float2 gc = sXY[t][kk];
                float dx = gc.x - px[k], dy = gc.y - py[k];
                float d2 = fmaf(dx, dx, dy * dy);
                if (k == 4) d2 = sub ? 3.0e38f : d2;
                float cc = __expf(2.0f - sqrtf(d2) * (2.0f / THR)) - 1.0f;
                acc += (d2 < THR2) ? cc : 0.0f;
            }
            acc += __shfl_xor_sync(FULL, acc, 16);
            silent |= ((hotbits >> p) & 1u) && (acc * inv_denK > SIL);
        }
    }

    // ---- 5b) rare general path for targets t in [32, nv)
    for (int t = 32; t < nv; t++) {
        float2 c0 = sXY[t][0];
        int gi = (int)floorf(c0.x * (1.0f / CELLW));
        int gj = (int)floorf(c0.y * (1.0f / CELLH));
        int sc = (gi >= 0 && gi < NW && gj >= 0 && gj < NH) ? gj * NW + gi : -1;
        thit = (sc == cell) ? t : thit;
        int cnt = 0;
        #pragma unroll
        for (int k = 0; k < 5; k++) {
            int kk = k + (sub ? 5 : 0); kk = kk > 8 ? 8 : kk;
            float2 gc = sXY[t][kk];
            float dx = gc.x - px[k], dy = gc.y - py[k];
            float d2 = fmaf(dx, dx, dy * dy);
            if (k == 4) d2 = sub ? 3.0e38f : d2;
            cnt += (d2 < GATE2);
        }
        cnt += __shfl_xor_sync(FULL, cnt, 16);
        bool hot = (cnt >= 5);
        if (__any_sync(FULL, hot)) {
            float acc = 0.0f;
            #pragma unroll
            for (int k = 0; k < 5; k++) {
                int kk = k + (sub ? 5 : 0); kk = kk > 8 ? 8 : kk;
                float2 gc = sXY[t][kk];
                float dx = gc.x - px[k], dy = gc.y - py[k];
                float d2 = fmaf(dx, dx, dy * dy);
                if (k == 4) d2 = sub ? 3.0e38f : d2;
                float cc = __expf(2.0f - sqrtf(d2) * (2.0f / THR)) - 1.0f;
                acc += (d2 < THR2) ? cc : 0.0f;
            }
            acc += __shfl_xor_sync(FULL, acc, 16);
            silent |= hot && (acc * inv_denK > SIL);
        }
    }

    // ---- 6) per-cell loss. Hit epilogue is WARP-UNIFORM (converged shuffles).
    float lcl = 0.0f;
    if (__any_sync(FULL, thit >= 0)) {
        const int th = (thit >= 0) ? thit : 0;
        float2 g0 = sXY[th][0];
        float gx0 = floorf(g0.x * (1.0f / CELLW));
        float gy0 = floorf(g0.y * (1.0f / CELLH));
        float closs = 0.0f, acc = 0.0f;
        #pragma unroll
        for (int k = 0; k < 5; k++) {
            int kk = k + (sub ? 5 : 0); kk = kk > 8 ? 8 : kk;
            float2 gc = sXY[th][kk];
            float w  = (sub && k == 4) ? 0.0f : 1.0f;   // mask dummy
            float ex = rx[k] - (gc.x * (1.0f / CELLW) - gx0);
            float ey = ry[k] - (gc.y * (1.0f / CELLH) - gy0);
            closs += 0.5f * w * (ex * ex + ey * ey);
            float dx = gc.x - px[k], dy = gc.y - py[k];
            float d2 = fmaf(dx, dx, dy * dy);
            if (k == 4) d2 = sub ? 3.0e38f : d2;
            float cc = __expf(2.0f - sqrtf(d2) * (2.0f / THR)) - 1.0f;
            acc += (d2 < THR2) ? cc : 0.0f;
        }
        acc += __shfl_xor_sync(FULL, acc, 16);          // converged pair combine
        if (thit >= 0) {
            lcl += closs;
            if (do_conf && !sub) {
                float e = confp - acc * inv_denK;
                lcl += 0.5f * OBJ * e * e;
            }
        }
    }
    if (thit < 0 && do_conf && !sub)
        lcl += silent ? 0.0f : 0.5f * confp * confp;    // NOOBJ, tconf = 0

    // ---- 7) warp -> block -> grid reduction
    #pragma unroll
    for (int o = 16; o > 0; o >>= 1)
        lcl += __shfl_xor_sync(FULL, lcl, o);
    if (lane == 0) swarp[wid] = lcl;
    __syncthreads();
    if (tid < 32) {                   // 32 warps per CTA
        float v = swarp[tid];
        #pragma unroll
        for (int o = 16; o > 0; o >>= 1)
            v += __shfl_xor_sync(FULL, v, o);
        if (tid == 0) {
            g_partials[bid] = v;
            __threadfence();
            unsigned old = atomicAdd(&g_count, 1);
            s_last = (old == NBLK - 1) ? 1 : 0;
        }
    }
    __syncthreads();
    if (s_last) {
        if (tid < NBLK) {             // 128 partials -> 4 warp sums
            float v = g_partials[tid];
            #pragma unroll
            for (int o = 16; o > 0; o >>= 1)
                v += __shfl_xor_sync(FULL, v, o);
            if ((tid & 31) == 0) swarp[tid >> 5] = v;
        }
        __syncthreads();
        if (tid == 0) {
            loss[0] = swarp[0] + swarp[1] + swarp[2] + swarp[3];
            g_count = 0;              // reset for next graph replay
        }
    }
}

extern "C" void kernel_launch(void* const* d_in, const int* in_sizes, int n_in,
                              void* d_out, int out_size)
{
    const float* output = (const float*)d_in[0];
    const float* target = (const float*)d_in[1];
    const int*   epoch  = (n_in > 2) ? (const int*)d_in[2] : nullptr;
    float* loss = (float*)d_out;

    region_loss_kernel<<<NBLK, TPB>>>(output, target, epoch, loss);
    (void)in_sizes; (void)out_size;
}

// round 12
// speedup vs baseline: 1.0528x; 1.0528x over previous
#include <cuda_runtime.h>

namespace {
constexpr int K     = 9;
constexpr int NB    = 64;
constexpr int NH    = 32;
constexpr int NW    = 32;
constexpr int NCELL = NH * NW;       // 1024
constexpr int NT    = 50;
constexpr int NLAB  = 2 * K + 3;     // 21
constexpr int CH    = 2 * K + 2;     // 20
constexpr float THR = 80.0f;
constexpr float IMW = 640.0f;
constexpr float IMH = 480.0f;
constexpr float SIL = 0.6f;
constexpr float OBJ = 5.0f;
constexpr int   TPB  = 1024;         // 2 threads per cell (paired lanes)
constexpr int   NBLK = 128;          // 128 CTAs, 1/SM, single wave
constexpr float CELLW = IMW / NW;    // 20 px
constexpr float CELLH = IMH / NH;    // 15 px
constexpr float THR2  = THR * THR;   // 6400
constexpr float GATE2 = 40.0f * 40.0f;  // silent needs >=5 corners within 40px
constexpr unsigned FULL = 0xffffffffu;
}

__device__ float        g_partials[NBLK];
__device__ unsigned int g_count = 0;

__global__ __launch_bounds__(TPB, 1) void region_loss_kernel(
    const float* __restrict__ out,
    const float* __restrict__ tgt,
    const int*   __restrict__ epoch_p,
    float*       __restrict__ loss)
{
    __shared__ float2 sXY[NT][10];                 // padded: col 9 = dummy
    __shared__ float swarp[TPB / 32];

    const int bid  = blockIdx.x;
    const int b    = bid >> 1;
    const int tid  = threadIdx.x;
    const int lane = tid & 31;
    const int sub  = lane >> 4;                    // 0: corners 0-4, 1: corners 5-8(+pad)
    const int wid  = tid >> 5;                     // warp covers 16 cells
    const int cell = ((bid & 1) << 9) | (wid << 4) | (lane & 15);
    const int wbase = cell & ~15;
    const int kbase = sub * 5;                     // corner index base

    // ---- 1) STAGING loads first (earliest L1tex queue slots -> early barrier)
    const float* tb = tgt + (size_t)b * (NT * NLAB);
    const bool do_stage = (tid < NT * 2 * K);
    int st = 0, sc = 0;
    float stg = 0.0f;
    if (do_stage) {
        st = tid / (2 * K); sc = tid - st * (2 * K);
        stg = tb[st * NLAB + 1 + sc];
    }
    const int epoch = epoch_p ? __ldg(epoch_p) : 20;

    // ---- 2) channel loads after (their latency overlaps post-barrier compute)
    const float* ob = out + (size_t)(b * CH) * NCELL + cell;
    float rx[5], ry[5];
    #pragma unroll
    for (int k = 0; k < 5; k++) {
        rx[k] = ob[(sub * 10 + 2 * k) * NCELL];
        ry[k] = ob[(sub * 10 + 2 * k + 1) * NCELL];
    }

    // smem store depends ONLY on the staging load (queue-front)
    if (do_stage) {
        float* dst = (float*)&sXY[st][sc >> 1];
        dst[sc & 1] = stg * ((sc & 1) ? IMH : IMW);
    }
    __syncthreads();

    // ---- 3) validity prefix + per-warp hit detection (lane-parallel, t<32)
    float2 c0l = sXY[lane][0];
    unsigned inv0 = ~__ballot_sync(FULL, c0l.x != 0.0f);
    bool v2 = (lane + 32 < NT) && (sXY[lane + 32][0].x != 0.0f);
    unsigned inv1 = ~__ballot_sync(FULL, v2);      // bits >= NT-32 always set
    const int nv = inv0 ? (__ffs(inv0) - 1) : (31 + __ffs(inv1));

    int gi0l = (int)floorf(c0l.x * (1.0f / CELLW));
    int gj0l = (int)floorf(c0l.y * (1.0f / CELLH));
    int cellv = (gi0l >= 0 && gi0l < NW && gj0l >= 0 && gj0l < NH)
                    ? gj0l * NW + gi0l : -1;
    cellv = (lane < nv) ? cellv : -1;
    unsigned hitm = __ballot_sync(FULL, (cellv >= wbase) && (cellv < wbase + 16));
    int thit = -1;
    for (unsigned hm = hitm; hm; hm &= hm - 1) {   // ascending t: last wins
        int t  = __ffs(hm) - 1;
        int sct = __shfl_sync(FULL, cellv, t);
        thit = (sct == cell) ? t : thit;
    }

    // ---- 4) predictions in pixel space (only global corner 0 is sigmoided)
    const bool do_conf = epoch > 15;
    const float i_f = (float)(cell & (NW - 1));
    const float j_f = (float)(cell >> 5);
    if (!sub) {
        rx[0] = 1.0f / (1.0f + __expf(-rx[0]));
        ry[0] = 1.0f / (1.0f + __expf(-ry[0]));
    }
    float confp = 1.0f / (1.0f + __expf(-__shfl_xor_sync(FULL, rx[4], 16)));

    float px[5], py[5];
    #pragma unroll
    for (int k = 0; k < 5; k++) {
        px[k] = (rx[k] + i_f) * CELLW;
        py[k] = (ry[k] + j_f) * CELLH;
    }

    const float inv_denK = (1.0f / (float)K) / (__expf(2.0f) - 1.0f + 1e-5f);

    // ---- 5) silent loop, targets t<32, groups of 8 with packed 4-bit counts
    bool silent = false;
    const int tmax = nv < 32 ? nv : 32;
    for (int g = 0; g < tmax; g += 8) {
        const int nvg = (tmax - g) < 8 ? (tmax - g) : 8;
        const unsigned vmask = (nvg == 8) ? 0x88888888u
                              : (((1u << (4 * nvg)) - 1u) & 0x88888888u);
        unsigned word = 0;
        #pragma unroll
        for (int tl = 0; tl < 8; tl++) {
            int t = g + tl;
            unsigned cnt = 0;
            #pragma unroll
            for (int k = 0; k < 5; k++) {
                float2 gc = sXY[t][kbase + k];
                float dx = gc.x - px[k], dy = gc.y - py[k];
                float d2 = fmaf(dx, dx, dy * dy);
                if (k == 4) d2 = sub ? 3.0e38f : d2;   // mask pad corner
                cnt += (d2 < GATE2);
            }
            word |= cnt << (4 * tl);
        }
        unsigned sum = word + __shfl_xor_sync(FULL, word, 16);  // nibbles <= 10
        unsigned hotbits = ((sum + 0x33333333u) & 0x88888888u) & vmask;
        unsigned un = __reduce_or_sync(FULL, hotbits);
        while (un) {                                            // rare, converged
            int p  = __ffs(un) - 1;
            un &= un - 1;
            int t  = g + (p >> 2);
            float acc = 0.0f;
            #pragma unroll
            for (int k = 0; k < 5; k++) {
                float2 gc = sXY[t][kbase + k];
                float dx = gc.x - px[k], dy = gc.y - py[k];
                float d2 = fmaf(dx, dx, dy * dy);
                if (k == 4) d2 = sub ? 3.0e38f : d2;
                float cc = __expf(2.0f - sqrtf(d2) * (2.0f / THR)) - 1.0f;
                acc += (d2 < THR2) ? cc : 0.0f;
            }
            acc += __shfl_xor_sync(FULL, acc, 16);
            silent |= ((hotbits >> p) & 1u) && (acc * inv_denK > SIL);
        }
    }

    // ---- 5b) rare general path for targets t in [32, nv)
    for (int t = 32; t < nv; t++) {
        float2 c0 = sXY[t][0];
        int gi = (int)floorf(c0.x * (1.0f / CELLW));
        int gj = (int)floorf(c0.y * (1.0f / CELLH));
        int sct = (gi >= 0 && gi < NW && gj >= 0 && gj < NH) ? gj * NW + gi : -1;
        thit = (sct == cell) ? t : thit;
        int cnt = 0;
        #pragma unroll
        for (int k = 0; k < 5; k++) {
            float2 gc = sXY[t][kbase + k];
            float dx = gc.x - px[k], dy = gc.y - py[k];
            float d2 = fmaf(dx, dx, dy * dy);
            if (k == 4) d2 = sub ? 3.0e38f : d2;
            cnt += (d2 < GATE2);
        }
        cnt += __shfl_xor_sync(FULL, cnt, 16);
        bool hot = (cnt >= 5);
        if (__any_sync(FULL, hot)) {
            float acc = 0.0f;
            #pragma unroll
            for (int k = 0; k < 5; k++) {
                float2 gc = sXY[t][kbase + k];
                float dx = gc.x - px[k], dy = gc.y - py[k];
                float d2 = fmaf(dx, dx, dy * dy);
                if (k == 4) d2 = sub ? 3.0e38f : d2;
                float cc = __expf(2.0f - sqrtf(d2) * (2.0f / THR)) - 1.0f;
                acc += (d2 < THR2) ? cc : 0.0f;
            }
            acc += __shfl_xor_sync(FULL, acc, 16);
            silent |= hot && (acc * inv_denK > SIL);
        }
    }

    // ---- 6) per-cell loss. Hit epilogue is WARP-UNIFORM (converged shuffles).
    float lcl = 0.0f;
    if (__any_sync(FULL, thit >= 0)) {
        const int th = (thit >= 0) ? thit : 0;
        float2 g0 = sXY[th][0];
        float gx0 = floorf(g0.x * (1.0f / CELLW));
        float gy0 = floorf(g0.y * (1.0f / CELLH));
        float closs = 0.0f, acc = 0.0f;
        #pragma unroll
        for (int k = 0; k < 5; k++) {
            float2 gc = sXY[th][kbase + k];
            float ex = rx[k] - (gc.x * (1.0f / CELLW) - gx0);
            float ey = ry[k] - (gc.y * (1.0f / CELLH) - gy0);
            // ternary (not *0) so pad-column garbage can never propagate NaN
            closs += (sub && k == 4) ? 0.0f : 0.5f * (ex * ex + ey * ey);
            float dx = gc.x - px[k], dy = gc.y - py[k];
            float d2 = fmaf(dx, dx, dy * dy);
            if (k == 4) d2 = sub ? 3.0e38f : d2;
            float cc = __expf(2.0f - sqrtf(d2) * (2.0f / THR)) - 1.0f;
            acc += (d2 < THR2) ? cc : 0.0f;
        }
        acc += __shfl_xor_sync(FULL, acc, 16);          // converged pair combine
        if (thit >= 0) {
            lcl += closs;
            if (do_conf && !sub) {
                float e = confp - acc * inv_denK;
                lcl += 0.5f * OBJ * e * e;
            }
        }
    }
    if (thit < 0 && do_conf && !sub)
        lcl += silent ? 0.0f : 0.5f * confp * confp;    // NOOBJ, tconf = 0

    // ---- 7) warp reduce -> swarp -> ONE barrier; only warp 0 continues.
    #pragma unroll
    for (int o = 16; o > 0; o >>= 1)
        lcl += __shfl_xor_sync(FULL, lcl, o);
    if (lane == 0) swarp[wid] = lcl;
    __syncthreads();
    if (tid >= 32) return;            // 31 warps exit; no tail barrier

    float v = swarp[tid];             // 32 warp partials
    #pragma unroll
    for (int o = 16; o > 0; o >>= 1)
        v += __shfl_xor_sync(FULL, v, o);
    int lastf = 0;
    if (tid == 0) {
        g_partials[bid] = v;
        __threadfence();
        lastf = (atomicAdd(&g_count, 1) == NBLK - 1) ? 1 : 0;
    }
    lastf = __shfl_sync(FULL, lastf, 0);
    if (lastf) {                      // last CTA's warp 0 does the final sum
        float s = g_partials[tid]      + g_partials[tid + 32]
                + g_partials[tid + 64] + g_partials[tid + 96];
        #pragma unroll
        for (int o = 16; o > 0; o >>= 1)
            s += __shfl_xor_sync(FULL, s, o);
        if (tid == 0) {
            loss[0] = s;
            g_count = 0;              // reset for next graph replay
        }
    }
}

extern "C" void kernel_launch(void* const* d_in, const int* in_sizes, int n_in,
                              void* d_out, int out_size)
{
    const float* output = (const float*)d_in[0];
    const float* target = (const float*)d_in[1];
    const int*   epoch  = (n_in > 2) ? (const int*)d_in[2] : nullptr;
    float* loss = (float*)d_out;

    region_loss_kernel<<<NBLK, TPB>>>(output, target, epoch, loss);
    (void)in_sizes; (void)out_size;
}